// round 7
// baseline (speedup 1.0000x reference)
#include <cuda_runtime.h>

typedef unsigned long long u64;

#define BB 2048
#define TT 4096
#define II 5
#define HH 10

// ---- packed fp32x2 helpers ----
__device__ __forceinline__ u64 pk2(float lo, float hi) {
    u64 r; asm("mov.b64 %0, {%1,%2};" : "=l"(r) : "f"(lo), "f"(hi)); return r;
}
__device__ __forceinline__ void upk2(u64 v, float &lo, float &hi) {
    asm("mov.b64 {%0,%1}, %2;" : "=f"(lo), "=f"(hi) : "l"(v));
}
__device__ __forceinline__ u64 fma2(u64 a, u64 b, u64 c) {
    u64 d; asm("fma.rn.f32x2 %0, %1, %2, %3;" : "=l"(d) : "l"(a), "l"(b), "l"(c)); return d;
}
__device__ __forceinline__ u64 add2(u64 a, u64 b) {
    u64 d; asm("add.rn.f32x2 %0, %1, %2;" : "=l"(d) : "l"(a), "l"(b)); return d;
}
__device__ __forceinline__ float tanhf_(float x) { float r; asm("tanh.approx.f32 %0, %1;" : "=f"(r) : "f"(x)); return r; }

// R6: latency HIDING instead of latency shaving. Each thread runs TWO
// independent batch elements (same hidden unit j); their serial chains
// interleave in one instruction stream, so two elements complete per chain
// latency L. Weights are per-unit -> both chains share every weight register.
// 512 warps (~1/SMSP on 128 SMs); smem h-broadcast as in R5.
__global__ void __launch_bounds__(128, 1) lstm_kernel(
    const float* __restrict__ x,   const float* __restrict__ h0,
    const float* __restrict__ c0,  const float* __restrict__ Wih,
    const float* __restrict__ Whh, const float* __restrict__ bih,
    const float* __restrict__ bhh, float* __restrict__ out)
{
    // 16 elements per CTA x 16 floats (64B stride: disjoint banks per element)
    __shared__ float hbuf[16][16];

    const int lane  = threadIdx.x & 31;
    const int wid   = threadIdx.x >> 5;                               // 0..3
    const int gwarp = (blockIdx.x * blockDim.x + threadIdx.x) >> 5;   // 0..511

    const int grp   = lane >> 4;            // lane-group: 0 or 1
    const int j     = lane & 15;            // unit index; >=10 idle
    const bool valid = (j < HH);
    const int jj    = valid ? j : 0;

    // two elements per thread
    const int e0 = gwarp * 4 + grp * 2;     // < 2048
    const int e1 = e0 + 1;
    const int slot0 = wid * 4 + grp * 2;    // smem slot 0..15
    const int slot1 = slot0 + 1;

    unsigned hbA_base, hbA_st, hbB_base, hbB_st;
    {
        unsigned b0, b1;
        asm("{ .reg .u64 t; cvta.to.shared.u64 t, %1; cvt.u32.u64 %0, t; }"
            : "=r"(b0) : "l"(&hbuf[slot0][0]));
        asm("{ .reg .u64 t; cvta.to.shared.u64 t, %1; cvt.u32.u64 %0, t; }"
            : "=r"(b1) : "l"(&hbuf[slot1][0]));
        hbA_base = b0; hbA_st = b0 + (unsigned)(j * 4);
        hbB_base = b1; hbB_st = b1 + (unsigned)(j * 4);
    }

    // ---- pre-scaled per-thread weights (SHARED by both chains) ----
    // gates i,f,o: x0.5 (sigmoid(x)=0.5+0.5*tanh(x/2)); gate g: x1.
    u64 wh[4][5];
    u64 wx01[4], wx23[4];
    float wx4[4], bs[4];
#pragma unroll
    for (int g = 0; g < 4; g++) {
        const float s = (g == 2) ? 1.0f : 0.5f;
        const int row = (g * HH + jj);
#pragma unroll
        for (int m = 0; m < 5; m++)
            wh[g][m] = pk2(s * Whh[row * HH + 2 * m], s * Whh[row * HH + 2 * m + 1]);
        wx01[g] = pk2(s * Wih[row * II + 0], s * Wih[row * II + 1]);
        wx23[g] = pk2(s * Wih[row * II + 2], s * Wih[row * II + 3]);
        wx4[g]  = s * Wih[row * II + 4];
        bs[g]   = s * (bih[g * HH + jj] + bhh[g * HH + jj]);
    }

    float hA = h0[e0 * HH + jj], cA = c0[e0 * HH + jj];
    float hB = h0[e1 * HH + jj], cB = c0[e1 * HH + jj];

    const float* xpA = x + (size_t)e0 * TT * II;
    const float* xpB = x + (size_t)e1 * TT * II;
    float* opA = out + (size_t)e0 * TT * HH + jj;
    float* opB = out + (size_t)e1 * TT * HH + jj;

    asm volatile("st.volatile.shared.f32 [%0], %1;" :: "r"(hbA_st), "f"(hA));
    asm volatile("st.volatile.shared.f32 [%0], %1;" :: "r"(hbB_st), "f"(hB));

    // x double buffers per element: 4 timesteps (20 floats) as 5 x float4.
    float xaA[20], xbA[20], xaB[20], xbB[20];
#pragma unroll
    for (int q = 0; q < 5; q++) {
        float4 vA = *reinterpret_cast<const float4*>(xpA + 4 * q);
        float4 vB = *reinterpret_cast<const float4*>(xpB + 4 * q);
        xaA[4*q+0]=vA.x; xaA[4*q+1]=vA.y; xaA[4*q+2]=vA.z; xaA[4*q+3]=vA.w;
        xaB[4*q+0]=vB.x; xaB[4*q+1]=vB.y; xaB[4*q+2]=vB.z; xaB[4*q+3]=vB.w;
    }

    // one interleaved step for BOTH elements
    auto STEP2 = [&](const float* xsA, const float* xsB, int t) {
        // 1) gather h for both chains (6 vector LDS, all issued up front)
        float a0,a1,a2,a3,a4,a5,a6,a7,a8,a9;
        float b0,b1,b2,b3,b4,b5,b6,b7,b8,b9;
        asm volatile("ld.volatile.shared.v4.f32 {%0,%1,%2,%3}, [%4];"
                     : "=f"(a0),"=f"(a1),"=f"(a2),"=f"(a3) : "r"(hbA_base));
        asm volatile("ld.volatile.shared.v4.f32 {%0,%1,%2,%3}, [%4];"
                     : "=f"(b0),"=f"(b1),"=f"(b2),"=f"(b3) : "r"(hbB_base));
        asm volatile("ld.volatile.shared.v4.f32 {%0,%1,%2,%3}, [%4+16];"
                     : "=f"(a4),"=f"(a5),"=f"(a6),"=f"(a7) : "r"(hbA_base));
        asm volatile("ld.volatile.shared.v4.f32 {%0,%1,%2,%3}, [%4+16];"
                     : "=f"(b4),"=f"(b5),"=f"(b6),"=f"(b7) : "r"(hbB_base));
        asm volatile("ld.volatile.shared.v2.f32 {%0,%1}, [%2+32];"
                     : "=f"(a8),"=f"(a9) : "r"(hbA_base));
        asm volatile("ld.volatile.shared.v2.f32 {%0,%1}, [%2+32];"
                     : "=f"(b8),"=f"(b9) : "r"(hbB_base));

        u64 hpA0=pk2(a0,a1), hpA1=pk2(a2,a3), hpA2=pk2(a4,a5), hpA3=pk2(a6,a7), hpA4=pk2(a8,a9);
        u64 hpB0=pk2(b0,b1), hpB1=pk2(b2,b3), hpB2=pk2(b4,b5), hpB3=pk2(b6,b7), hpB4=pk2(b8,b9);

        // 2) x-parts (independent of h; fill the LDS shadow)
        u64 xA01 = pk2(xsA[0], xsA[1]), xA23 = pk2(xsA[2], xsA[3]);
        u64 xB01 = pk2(xsB[0], xsB[1]), xB23 = pk2(xsB[2], xsB[3]);
        const float xA4 = xsA[4], xB4 = xsB[4];

        float preA[4], preB[4];
#pragma unroll
        for (int g = 0; g < 4; g++) {
            float tgA = fmaf(wx4[g], xA4, bs[g]);
            float tgB = fmaf(wx4[g], xB4, bs[g]);
            u64 aA = fma2(wx23[g], xA23, pk2(tgA, 0.0f));
            u64 aB = fma2(wx23[g], xB23, pk2(tgB, 0.0f));
            u64 dA = fma2(wx01[g], xA01, pk2(0.0f, 0.0f));
            u64 dB = fma2(wx01[g], xB01, pk2(0.0f, 0.0f));
            aA = fma2(wh[g][0], hpA0, aA);   aB = fma2(wh[g][0], hpB0, aB);
            dA = fma2(wh[g][1], hpA1, dA);   dB = fma2(wh[g][1], hpB1, dB);
            aA = fma2(wh[g][2], hpA2, aA);   aB = fma2(wh[g][2], hpB2, aB);
            dA = fma2(wh[g][3], hpA3, dA);   dB = fma2(wh[g][3], hpB3, dB);
            aA = fma2(wh[g][4], hpA4, aA);   aB = fma2(wh[g][4], hpB4, aB);
            u64 sA = add2(aA, dA), sB = add2(aB, dB);
            float loA, hiA, loB, hiB;
            upk2(sA, loA, hiA); upk2(sB, loB, hiB);
            preA[g] = loA + hiA; preB[g] = loB + hiB;
        }

        // 3) activations, interleaved (MUFU queue alternates chains)
        float siA = fmaf(0.5f, tanhf_(preA[0]), 0.5f);
        float siB = fmaf(0.5f, tanhf_(preB[0]), 0.5f);
        float sfA = fmaf(0.5f, tanhf_(preA[1]), 0.5f);
        float sfB = fmaf(0.5f, tanhf_(preB[1]), 0.5f);
        float ggA = tanhf_(preA[2]);
        float ggB = tanhf_(preB[2]);
        float soA = fmaf(0.5f, tanhf_(preA[3]), 0.5f);
        float soB = fmaf(0.5f, tanhf_(preB[3]), 0.5f);
        cA = fmaf(sfA, cA, siA * ggA);
        cB = fmaf(sfB, cB, siB * ggB);
        hA = soA * tanhf_(cA);
        hB = soB * tanhf_(cB);

        // 4) publish + output
        asm volatile("st.volatile.shared.f32 [%0], %1;" :: "r"(hbA_st), "f"(hA));
        asm volatile("st.volatile.shared.f32 [%0], %1;" :: "r"(hbB_st), "f"(hB));
        if (valid) {
            opA[(size_t)t * HH] = hA;
            opB[(size_t)t * HH] = hB;
        }
    };

    for (int tb = 0; tb < TT; tb += 8) {
#pragma unroll
        for (int q = 0; q < 5; q++) {
            float4 vA = *reinterpret_cast<const float4*>(xpA + (tb + 4) * II + 4 * q);
            float4 vB = *reinterpret_cast<const float4*>(xpB + (tb + 4) * II + 4 * q);
            xbA[4*q+0]=vA.x; xbA[4*q+1]=vA.y; xbA[4*q+2]=vA.z; xbA[4*q+3]=vA.w;
            xbB[4*q+0]=vB.x; xbB[4*q+1]=vB.y; xbB[4*q+2]=vB.z; xbB[4*q+3]=vB.w;
        }
#pragma unroll
        for (int s = 0; s < 4; s++)
            STEP2(&xaA[s * 5], &xaB[s * 5], tb + s);

        if (tb + 8 < TT) {
#pragma unroll
            for (int q = 0; q < 5; q++) {
                float4 vA = *reinterpret_cast<const float4*>(xpA + (tb + 8) * II + 4 * q);
                float4 vB = *reinterpret_cast<const float4*>(xpB + (tb + 8) * II + 4 * q);
                xaA[4*q+0]=vA.x; xaA[4*q+1]=vA.y; xaA[4*q+2]=vA.z; xaA[4*q+3]=vA.w;
                xaB[4*q+0]=vB.x; xaB[4*q+1]=vB.y; xaB[4*q+2]=vB.z; xaB[4*q+3]=vB.w;
            }
        }
#pragma unroll
        for (int s = 0; s < 4; s++)
            STEP2(&xbA[s * 5], &xbB[s * 5], tb + 4 + s);
    }
}

extern "C" void kernel_launch(void* const* d_in, const int* in_sizes, int n_in,
                              void* d_out, int out_size)
{
    const float* x   = (const float*)d_in[0];
    const float* h0  = (const float*)d_in[1];
    const float* c0  = (const float*)d_in[2];
    const float* Wih = (const float*)d_in[3];
    const float* Whh = (const float*)d_in[4];
    const float* bih = (const float*)d_in[5];
    const float* bhh = (const float*)d_in[6];
    float* out = (float*)d_out;

    // 512 warps: 4 elements per warp (2 lane-groups x 2 elements/thread).
    const int threads = 128;
    const int blocks  = (BB / 4) * 32 / threads;   // 128
    lstm_kernel<<<blocks, threads>>>(x, h0, c0, Wih, Whh, bih, bhh, out);
}

// round 9
// speedup vs baseline: 1.3873x; 1.3873x over previous
#include <cuda_runtime.h>

typedef unsigned long long u64;

#define BB 2048
#define TT 4096
#define II 5
#define HH 10

// ---- packed fp32x2 helpers ----
__device__ __forceinline__ u64 pk2(float lo, float hi) {
    u64 r; asm("mov.b64 %0, {%1,%2};" : "=l"(r) : "f"(lo), "f"(hi)); return r;
}
__device__ __forceinline__ void upk2(u64 v, float &lo, float &hi) {
    asm("mov.b64 {%0,%1}, %2;" : "=f"(lo), "=f"(hi) : "l"(v));
}
__device__ __forceinline__ u64 fma2(u64 a, u64 b, u64 c) {
    u64 d; asm("fma.rn.f32x2 %0, %1, %2, %3;" : "=l"(d) : "l"(a), "l"(b), "l"(c)); return d;
}
__device__ __forceinline__ u64 mul2(u64 a, u64 b) {
    u64 d; asm("mul.rn.f32x2 %0, %1, %2;" : "=l"(d) : "l"(a), "l"(b)); return d;
}
__device__ __forceinline__ u64 add2(u64 a, u64 b) {
    u64 d; asm("add.rn.f32x2 %0, %1, %2;" : "=l"(d) : "l"(a), "l"(b)); return d;
}
__device__ __forceinline__ float tanhf_(float x) { float r; asm("tanh.approx.f32 %0, %1;" : "=f"(r) : "f"(x)); return r; }

// R7 = R5 structure (16 lanes/element, 2 elements/warp via lane-SIMD, 1024
// warps, smem h-broadcast) with T_step micro-surgery:
//  - 3 accumulation chains per gate keyed to LDS arrival order
//  - o-gate MUFU issued first, tanh(c) last
//  - non-volatile smem ops (compiler-ordered; per-warp smem is in-order)
//  - x prefetched 8 steps at a time
__global__ void __launch_bounds__(128, 1) lstm_kernel(
    const float* __restrict__ x,   const float* __restrict__ h0,
    const float* __restrict__ c0,  const float* __restrict__ Wih,
    const float* __restrict__ Whh, const float* __restrict__ bih,
    const float* __restrict__ bhh, float* __restrict__ out)
{
    // 8 elements per CTA x 16 floats (64B stride -> disjoint banks)
    __shared__ float hbuf[8][16];

    const int lane  = threadIdx.x & 31;
    const int gwarp = (blockIdx.x * blockDim.x + threadIdx.x) >> 5;   // 0..1023

    const int grp   = lane >> 4;            // element within warp: 0 or 1
    const int j     = lane & 15;            // unit index; >=10 idle
    const bool valid = (j < HH);
    const int jj    = valid ? j : 0;
    const int b     = gwarp * 2 + grp;      // < 2048
    const int elem  = ((threadIdx.x >> 5) << 1) + grp;   // 0..7 in CTA

    unsigned hb_store, hb_base;
    {
        unsigned base;
        asm("{ .reg .u64 t; cvta.to.shared.u64 t, %1; cvt.u32.u64 %0, t; }"
            : "=r"(base) : "l"(&hbuf[elem][0]));
        hb_base  = base;
        hb_store = base + (unsigned)(j * 4);
    }

    // ---- pre-scaled per-thread weights ----
    // gates i,f,o: x0.5 (sigmoid(x)=0.5+0.5*tanh(x/2)); gate g: x1.
    u64 wh[4][5];
    u64 wx01[4], wx23[4];
    float wx4[4], bs[4];
#pragma unroll
    for (int g = 0; g < 4; g++) {
        const float s = (g == 2) ? 1.0f : 0.5f;
        const int row = (g * HH + jj);
#pragma unroll
        for (int m = 0; m < 5; m++)
            wh[g][m] = pk2(s * Whh[row * HH + 2 * m], s * Whh[row * HH + 2 * m + 1]);
        wx01[g] = pk2(s * Wih[row * II + 0], s * Wih[row * II + 1]);
        wx23[g] = pk2(s * Wih[row * II + 2], s * Wih[row * II + 3]);
        wx4[g]  = s * Wih[row * II + 4];
        bs[g]   = s * (bih[g * HH + jj] + bhh[g * HH + jj]);
    }

    float h = h0[b * HH + jj];
    float c = c0[b * HH + jj];

    const float* xp = x   + (size_t)b * TT * II;
    float*       op = out + (size_t)b * TT * HH + jj;

    asm volatile("st.shared.f32 [%0], %1;" :: "r"(hb_store), "f"(h));

    // x double buffers: 8 timesteps (40 floats) each, as 10 x float4.
    // (b*T + t)*I*4B is 16B-aligned whenever t%4==0.
    float xa[40], xb[40];
#pragma unroll
    for (int q = 0; q < 10; q++) {
        float4 v = *reinterpret_cast<const float4*>(xp + 4 * q);
        xa[4*q+0]=v.x; xa[4*q+1]=v.y; xa[4*q+2]=v.z; xa[4*q+3]=v.w;
    }

    auto STEP = [&](const float* xs, int t) {
        // 1) gather h: 3 LDS issued up front; chains start per-arrival
        float h0_,h1_,h2_,h3_,h4_,h5_,h6_,h7_,h8_,h9_;
        asm volatile("ld.shared.v4.f32 {%0,%1,%2,%3}, [%4];"
                     : "=f"(h0_),"=f"(h1_),"=f"(h2_),"=f"(h3_) : "r"(hb_base));
        asm volatile("ld.shared.v4.f32 {%0,%1,%2,%3}, [%4+16];"
                     : "=f"(h4_),"=f"(h5_),"=f"(h6_),"=f"(h7_) : "r"(hb_base));
        asm volatile("ld.shared.v2.f32 {%0,%1}, [%2+32];"
                     : "=f"(h8_),"=f"(h9_) : "r"(hb_base));
        u64 hp0=pk2(h0_,h1_), hp1=pk2(h2_,h3_), hp2=pk2(h4_,h5_),
            hp3=pk2(h6_,h7_), hp4=pk2(h8_,h9_);

        // 2) x-part (off-chain; fills the LDS shadow)
        u64 x01 = pk2(xs[0], xs[1]);
        u64 x23 = pk2(xs[2], xs[3]);
        const float x4 = xs[4];

        float pre[4];
#pragma unroll
        for (int g = 0; g < 4; g++) {
            // chain e: x-part + hp4 (hp4 lands last; e is ready to absorb it)
            u64 e = fma2(wx01[g], x01, mul2(wx23[g], x23));
            // chain a: hp0,hp1 (first v4) ; chain d: hp2,hp3 (second v4)
            u64 a = fma2(wh[g][1], hp1, mul2(wh[g][0], hp0));
            u64 d = fma2(wh[g][3], hp3, mul2(wh[g][2], hp2));
            e = fma2(wh[g][4], hp4, e);
            u64 s2 = add2(add2(a, d), e);
            float lo, hi; upk2(s2, lo, hi);
            float tg = fmaf(wx4[g], x4, bs[g]);
            pre[g] = (lo + hi) + tg;
        }

        // 3) activations: o first (consumed last), tanh(c) last
        float to  = tanhf_(pre[3]);
        float si  = fmaf(0.5f, tanhf_(pre[0]), 0.5f);
        float sf  = fmaf(0.5f, tanhf_(pre[1]), 0.5f);
        float gg  = tanhf_(pre[2]);
        c = fmaf(sf, c, si * gg);
        float so  = fmaf(0.5f, to, 0.5f);
        h = so * tanhf_(c);

        // 4) publish + output
        asm volatile("st.shared.f32 [%0], %1;" :: "r"(hb_store), "f"(h));
        if (valid) op[(size_t)t * HH] = h;
    };

    for (int tb = 0; tb < TT; tb += 16) {
        // prefetch next 8 steps into xb while computing from xa
#pragma unroll
        for (int q = 0; q < 10; q++) {
            float4 v = *reinterpret_cast<const float4*>(xp + (tb + 8) * II + 4 * q);
            xb[4*q+0]=v.x; xb[4*q+1]=v.y; xb[4*q+2]=v.z; xb[4*q+3]=v.w;
        }
#pragma unroll
        for (int s = 0; s < 8; s++)
            STEP(&xa[s * 5], tb + s);

        if (tb + 16 < TT) {
#pragma unroll
            for (int q = 0; q < 10; q++) {
                float4 v = *reinterpret_cast<const float4*>(xp + (tb + 16) * II + 4 * q);
                xa[4*q+0]=v.x; xa[4*q+1]=v.y; xa[4*q+2]=v.z; xa[4*q+3]=v.w;
            }
        }
#pragma unroll
        for (int s = 0; s < 8; s++)
            STEP(&xb[s * 5], tb + 8 + s);
    }
}

extern "C" void kernel_launch(void* const* d_in, const int* in_sizes, int n_in,
                              void* d_out, int out_size)
{
    const float* x   = (const float*)d_in[0];
    const float* h0  = (const float*)d_in[1];
    const float* c0  = (const float*)d_in[2];
    const float* Wih = (const float*)d_in[3];
    const float* Whh = (const float*)d_in[4];
    const float* bih = (const float*)d_in[5];
    const float* bhh = (const float*)d_in[6];
    float* out = (float*)d_out;

    // 1024 warps: 2 elements per warp (lane-SIMD), 16 lanes per element.
    const int threads = 128;
    const int blocks  = (BB / 2) * 32 / threads;   // 256
    lstm_kernel<<<blocks, threads>>>(x, h0, c0, Wih, Whh, bih, bhh, out);
}